// round 14
// baseline (speedup 1.0000x reference)
#include <cuda_runtime.h>
#include <cuda_fp16.h>
#include <cstdint>

// Problem shape (fixed by the dataset)
#define NMAX 100000
#define EMAX 1600000
#define INC 128
#define HIDC 128
#define OUTC 64

// ---------------- scratch (no allocation allowed) ----------------
__device__ __half g_h1[(size_t)NMAX * HIDC];  // x@W1 (unscaled, fp16)
__device__ __half g_hr[(size_t)NMAX * HIDC];  // relu(agg1 + b1), fp16
__device__ __half g_h2[(size_t)NMAX * OUTC];  // hr@W2 (unscaled, fp16)
__device__ float  g_dinv[NMAX];
__device__ float  g_edinv[EMAX];              // per-edge dinv[src], CSR order
__device__ int    g_cnt[2 * NMAX + 1];        // [0,N): in-deg, [NMAX,NMAX+N): out-deg, [2*NMAX]: total
__device__ int    g_rowstart[NMAX];
__device__ int    g_cursor[NMAX];
__device__ int    g_csr[EMAX];

// ---------------- helpers ----------------
__device__ __forceinline__ uint32_t pack_half2(float a, float b) {
    __half2 h = __floats2half2_rn(a, b);
    return *reinterpret_cast<uint32_t*>(&h);
}

__device__ __forceinline__ void mma_fp16(float* c, uint32_t a0, uint32_t a1,
                                         uint32_t a2, uint32_t a3,
                                         uint32_t b0, uint32_t b1) {
    asm volatile(
        "mma.sync.aligned.m16n8k16.row.col.f32.f16.f16.f32 "
        "{%0,%1,%2,%3}, {%4,%5,%6,%7}, {%8,%9}, {%0,%1,%2,%3};"
        : "+f"(c[0]), "+f"(c[1]), "+f"(c[2]), "+f"(c[3])
        : "r"(a0), "r"(a1), "r"(a2), "r"(a3), "r"(b0), "r"(b1));
}

// ---------------- CSR build (x4-unrolled atomics: independent chains) ----------------
__global__ void hist_kernel(const int* __restrict__ ei, int E) {
    int q = blockIdx.x * blockDim.x + threadIdx.x;
    int e0 = q * 4;
    if (e0 + 4 <= E) {
        int4 s = *(const int4*)(ei + e0);
        int4 d = *(const int4*)(ei + E + e0);
        atomicAdd(&g_cnt[NMAX + s.x], 1);
        atomicAdd(&g_cnt[NMAX + s.y], 1);
        atomicAdd(&g_cnt[NMAX + s.z], 1);
        atomicAdd(&g_cnt[NMAX + s.w], 1);
        atomicAdd(&g_cnt[d.x], 1);
        atomicAdd(&g_cnt[d.y], 1);
        atomicAdd(&g_cnt[d.z], 1);
        atomicAdd(&g_cnt[d.w], 1);
    } else {
        for (int e = e0; e < E; e++) {
            atomicAdd(&g_cnt[NMAX + ei[e]], 1);
            atomicAdd(&g_cnt[ei[E + e]], 1);
        }
    }
}

// Fused scan: block-local shuffle scan + one atomic segment allocation per block.
__global__ void alloc_scan_kernel(int n) {
    __shared__ int wsum[32];
    __shared__ int sbase;
    int t = threadIdx.x, lane = t & 31, w = t >> 5;
    int gid = blockIdx.x * 1024 + t;
    int v = (gid < n) ? g_cnt[gid] : 0;
    int x = v;
    #pragma unroll
    for (int d = 1; d < 32; d <<= 1) {
        int y = __shfl_up_sync(0xFFFFFFFFu, x, d);
        if (lane >= d) x += y;
    }
    if (lane == 31) wsum[w] = x;
    __syncthreads();
    if (w == 0) {
        int s = wsum[lane];
        int xs = s;
        #pragma unroll
        for (int d = 1; d < 32; d <<= 1) {
            int y = __shfl_up_sync(0xFFFFFFFFu, xs, d);
            if (lane >= d) xs += y;
        }
        wsum[lane] = xs - s;
    }
    __syncthreads();
    int excl = x - v + wsum[w];
    if (t == 1023) sbase = atomicAdd(&g_cnt[2 * NMAX], excl + v);
    __syncthreads();
    if (gid < n) {
        int base = sbase + excl;
        g_rowstart[gid] = base;
        g_cursor[gid] = base;
        int d = g_cnt[NMAX + gid];
        g_dinv[gid] = 1.0f / (float)(d > 1 ? d : 1);
    }
}

// scatter also materializes per-edge dinv (runs on the hidden CSR chain)
__global__ void scatter_kernel(const int* __restrict__ ei, int E) {
    int q = blockIdx.x * blockDim.x + threadIdx.x;
    int e0 = q * 4;
    if (e0 + 4 <= E) {
        int4 s = *(const int4*)(ei + e0);
        int4 d = *(const int4*)(ei + E + e0);
        float v0 = __ldg(&g_dinv[s.x]);
        float v1 = __ldg(&g_dinv[s.y]);
        float v2 = __ldg(&g_dinv[s.z]);
        float v3 = __ldg(&g_dinv[s.w]);
        int p0 = atomicAdd(&g_cursor[d.x], 1);
        int p1 = atomicAdd(&g_cursor[d.y], 1);
        int p2 = atomicAdd(&g_cursor[d.z], 1);
        int p3 = atomicAdd(&g_cursor[d.w], 1);
        g_csr[p0] = s.x;
        g_csr[p1] = s.y;
        g_csr[p2] = s.z;
        g_csr[p3] = s.w;
        g_edinv[p0] = v0;
        g_edinv[p1] = v1;
        g_edinv[p2] = v2;
        g_edinv[p3] = v3;
    } else {
        for (int e = e0; e < E; e++) {
            int ss = ei[e];
            int dd = ei[E + e];
            int pos = atomicAdd(&g_cursor[dd], 1);
            g_csr[pos] = ss;
            g_edinv[pos] = __ldg(&g_dinv[ss]);
        }
    }
}

// ---------------- fp16 mma.sync m16n8k16 GEMM (round-12 persistent, SAW=72) ----------
// out_fp16[M,N_] = A[M,128] @ W[128,N_]
// A smem: row stride SAW=72 words (conflict-free fragment LDS.64).
// B smem: unit (n,u) at word ((u>>3)*N_ + n)*8 + p(u&7), p(v)=v<4?2v:2(v-4)+1.
#define SAW 72

template <int N_, bool FIRST>
__global__ __launch_bounds__(256, 2)
void gemm_mma_kernel(const float* __restrict__ Ain, const float* __restrict__ W,
                     int M, int n_tiles) {
    extern __shared__ uint32_t smem[];
    uint32_t* As = smem;                  // 64 * SAW words
    uint32_t* Bs = smem + 64 * SAW;       // 64 * N_ words

    __half* __restrict__ out = FIRST ? g_h1 : g_h2;

    constexpr int HALF = N_ / 2;
    constexpr int NT = HALF / 8;          // 8 for N=128, 4 for N=64
    const int tid = threadIdx.x;
    const int wid = tid >> 5;             // 0..7
    const int lane = tid & 31;
    const int qr = lane >> 2;
    const int qc = lane & 3;
    const int rg = wid & 3;               // row group (16 rows)
    const int cg = wid >> 2;              // col half

    // ---- stage B once ----
    for (int uidx = tid; uidx < 64 * N_; uidx += 256) {
        int u = uidx / N_;
        int n = uidx - u * N_;
        uint32_t val = pack_half2(W[(size_t)(2 * u) * N_ + n], W[(size_t)(2 * u + 1) * N_ + n]);
        int v = u & 7;
        int p = (v < 4) ? (2 * v) : (2 * (v - 4) + 1);
        Bs[(((u >> 3) * N_ + n) << 3) + p] = val;
    }

    const int sg = lane >> 2;
    const int sj = lane & 3;

    auto load_row = [&](int gr, uint32_t& r0, uint32_t& r1) {
        if (gr >= M) { r0 = 0u; r1 = 0u; return; }
        if constexpr (FIRST) {
            float4 v = *(const float4*)(Ain + (size_t)gr * 128 + lane * 4);
            r0 = pack_half2(v.x, v.y);
            r1 = pack_half2(v.z, v.w);
        } else {
            uint2 u = *(const uint2*)(g_hr + (size_t)gr * 128 + lane * 4);
            r0 = u.x; r1 = u.y;
        }
    };

    uint32_t pr0[8], pr1[8];
    int t = blockIdx.x;
    if (t < n_tiles) {
        #pragma unroll
        for (int it = 0; it < 8; it++)
            load_row(t * 64 + wid + it * 8, pr0[it], pr1[it]);
    }
    __syncthreads();   // B staged

    for (; t < n_tiles; ) {
        // ---- STS: lane-pair (xor 2) exchange -> conflict-free STS.128 ----
        #pragma unroll
        for (int it = 0; it < 8; it++) {
            int r = wid + it * 8;
            uint32_t o0 = __shfl_xor_sync(0xFFFFFFFFu, pr0[it], 2);
            uint32_t o1 = __shfl_xor_sync(0xFFFFFFFFu, pr1[it], 2);
            if ((sj & 2) == 0) {
                uint4 st;
                st.x = pr0[it]; st.y = o0; st.z = pr1[it]; st.w = o1;
                *(uint4*)(As + r * SAW + sg * 8 + (sj & 1) * 4) = st;
            }
        }
        __syncthreads();

        // ---- prefetch next tile (overlaps compute) ----
        int tn = t + gridDim.x;
        if (tn < n_tiles) {
            #pragma unroll
            for (int it = 0; it < 8; it++)
                load_row(tn * 64 + wid + it * 8, pr0[it], pr1[it]);
        }

        // ---- compute: 8 k16-steps ----
        float acc[NT][4];
        #pragma unroll
        for (int nt = 0; nt < NT; nt++)
            #pragma unroll
            for (int j = 0; j < 4; j++) acc[nt][j] = 0.f;

        #pragma unroll
        for (int s = 0; s < 8; s++) {
            const uint32_t* pa = As + (rg * 16 + qr) * SAW + s * 8 + qc * 2;
            uint2 A0 = *(const uint2*)pa;              // {a0, a2}
            uint2 A1 = *(const uint2*)(pa + 8 * SAW);  // {a1, a3}
            const uint32_t* pb = Bs + (((s * N_) + cg * HALF + qr) << 3) + qc * 2;
            #pragma unroll
            for (int nt = 0; nt < NT; nt++) {
                uint2 B0 = *(const uint2*)(pb + (nt << 6));
                mma_fp16(acc[nt], A0.x, A1.x, A0.y, A1.y, B0.x, B0.y);
            }
        }

        // ---- epilogue: fp16 store ----
        {
            int r0 = t * 64 + rg * 16 + qr;
            int r1 = r0 + 8;
            #pragma unroll
            for (int nt = 0; nt < NT; nt++) {
                int c = cg * HALF + nt * 8 + qc * 2;
                if (r0 < M)
                    *(__half2*)(out + (size_t)r0 * N_ + c) = __floats2half2_rn(acc[nt][0], acc[nt][1]);
                if (r1 < M)
                    *(__half2*)(out + (size_t)r1 * N_ + c) = __floats2half2_rn(acc[nt][2], acc[nt][3]);
            }
        }
        __syncthreads();
        t = tn;
    }
}

// ---------------- aggregation: warp per dst node, fully-predicated 8-wide loop ----------------
template <int C, bool FIRST>
__global__ void agg_kernel(const float* __restrict__ bias, float* __restrict__ outp, int n) {
    int gw = (blockIdx.x * blockDim.x + threadIdx.x) >> 5;
    int lane = threadIdx.x & 31;
    if (gw >= n) return;

    const __half* __restrict__ h = FIRST ? g_h1 : g_h2;

    int beg = g_rowstart[gw];
    int m = g_cnt[gw];   // in-degree

    if constexpr (C == 128) {
        size_t off = (size_t)lane * 4;
        float4 acc = make_float4(0.f, 0.f, 0.f, 0.f);
        for (int e = 0; e < m; e += 8) {
            int pos[8];
            int idx[8];
            uint2 u[8];
            float d[8];
            #pragma unroll
            for (int j = 0; j < 8; j++) {
                int ee = e + j;
                pos[j] = beg + ((ee < m) ? ee : e);   // clamp to a valid slot
            }
            #pragma unroll
            for (int j = 0; j < 8; j++) idx[j] = g_csr[pos[j]];
            #pragma unroll
            for (int j = 0; j < 8; j++) u[j] = *(const uint2*)(h + (size_t)idx[j] * C + off);
            #pragma unroll
            for (int j = 0; j < 8; j++) d[j] = (e + j < m) ? g_edinv[pos[j]] : 0.f;
            #pragma unroll
            for (int j = 0; j < 8; j++) {
                float2 a0 = __half22float2(*reinterpret_cast<__half2*>(&u[j].x));
                float2 a1 = __half22float2(*reinterpret_cast<__half2*>(&u[j].y));
                acc.x = fmaf(a0.x, d[j], acc.x);
                acc.y = fmaf(a0.y, d[j], acc.y);
                acc.z = fmaf(a1.x, d[j], acc.z);
                acc.w = fmaf(a1.y, d[j], acc.w);
            }
        }
        float4 bb = *(const float4*)(bias + lane * 4);
        acc.x += bb.x; acc.y += bb.y; acc.z += bb.z; acc.w += bb.w;
        if constexpr (FIRST) {
            acc.x = fmaxf(acc.x, 0.f); acc.y = fmaxf(acc.y, 0.f);
            acc.z = fmaxf(acc.z, 0.f); acc.w = fmaxf(acc.w, 0.f);
            uint2 st;
            *reinterpret_cast<__half2*>(&st.x) = __floats2half2_rn(acc.x, acc.y);
            *reinterpret_cast<__half2*>(&st.y) = __floats2half2_rn(acc.z, acc.w);
            *(uint2*)(g_hr + (size_t)gw * C + off) = st;
        } else {
            *(float4*)(outp + (size_t)gw * C + off) = acc;
        }
    } else {
        size_t off = (size_t)lane * 2;
        float2 acc = make_float2(0.f, 0.f);
        for (int e = 0; e < m; e += 8) {
            int pos[8];
            int idx[8];
            uint32_t u[8];
            float d[8];
            #pragma unroll
            for (int j = 0; j < 8; j++) {
                int ee = e + j;
                pos[j] = beg + ((ee < m) ? ee : e);
            }
            #pragma unroll
            for (int j = 0; j < 8; j++) idx[j] = g_csr[pos[j]];
            #pragma unroll
            for (int j = 0; j < 8; j++) u[j] = *(const uint32_t*)(h + (size_t)idx[j] * C + off);
            #pragma unroll
            for (int j = 0; j < 8; j++) d[j] = (e + j < m) ? g_edinv[pos[j]] : 0.f;
            #pragma unroll
            for (int j = 0; j < 8; j++) {
                float2 a = __half22float2(*reinterpret_cast<__half2*>(&u[j]));
                acc.x = fmaf(a.x, d[j], acc.x);
                acc.y = fmaf(a.y, d[j], acc.y);
            }
        }
        float2 bb = *(const float2*)(bias + lane * 2);
        acc.x += bb.x; acc.y += bb.y;
        *(float2*)(outp + (size_t)gw * C + off) = acc;
    }
}

// ---------------- launch ----------------
extern "C" void kernel_launch(void* const* d_in, const int* in_sizes, int n_in,
                              void* d_out, int out_size) {
    const float* x  = (const float*)d_in[0];
    const int*   ei = (const int*)d_in[1];
    const float* W1 = (const float*)d_in[2];
    const float* b1 = (const float*)d_in[3];
    const float* W2 = (const float*)d_in[4];
    const float* b2 = (const float*)d_in[5];
    float* out = (float*)d_out;

    int N = in_sizes[0] / INC;   // 100000
    int E = in_sizes[1] / 2;     // 1600000

    int nb1k = (N + 1023) / 1024;
    int n_tiles = (N + 63) / 64;

    const int SMEM1 = (64 * SAW + 64 * HIDC) * 4;   // 51200 (~50KB)
    const int SMEM2 = (64 * SAW + 64 * OUTC) * 4;   // 34816 (~34KB)

    static int sm_count = 0;
    static cudaStream_t s2 = nullptr;
    static cudaEvent_t evFork = nullptr, evCsr = nullptr;
    static void *p_cnt = nullptr;
    static bool init_ok = false;
    if (!init_ok) {
        int dev = 0, c = 0;
        cudaGetDevice(&dev);
        if (cudaDeviceGetAttribute(&c, cudaDevAttrMultiProcessorCount, dev) != cudaSuccess || c <= 0)
            c = 148;
        sm_count = c;
        cudaFuncSetAttribute(gemm_mma_kernel<HIDC, true>,
                             cudaFuncAttributeMaxDynamicSharedMemorySize, SMEM1);
        cudaFuncSetAttribute(gemm_mma_kernel<OUTC, false>,
                             cudaFuncAttributeMaxDynamicSharedMemorySize, SMEM2);
        cudaStreamCreateWithFlags(&s2, cudaStreamNonBlocking);
        cudaEventCreateWithFlags(&evFork, cudaEventDisableTiming);
        cudaEventCreateWithFlags(&evCsr,  cudaEventDisableTiming);
        cudaGetSymbolAddress(&p_cnt, g_cnt);
        init_ok = true;
    }

    int gemm_grid = 2 * sm_count;   // 2 CTAs/SM

    // ---- fork: CSR chain on s2 (atomics/latency-bound), GEMM1 on main (DRAM/tensor) ----
    cudaEventRecord(evFork, 0);
    cudaStreamWaitEvent(s2, evFork, 0);

    cudaMemsetAsync(p_cnt, 0, (size_t)(2 * NMAX + 1) * sizeof(int), s2);
    hist_kernel<<<(E / 4 + 255) / 256 + 1, 256, 0, s2>>>(ei, E);
    alloc_scan_kernel<<<nb1k, 1024, 0, s2>>>(N);
    scatter_kernel<<<(E / 4 + 255) / 256 + 1, 256, 0, s2>>>(ei, E);
    cudaEventRecord(evCsr, s2);

    gemm_mma_kernel<HIDC, true><<<gemm_grid, 256, SMEM1, 0>>>(x, W1, N, n_tiles);

    // ---- join, then serial memory-bound tail ----
    cudaStreamWaitEvent(0, evCsr, 0);
    agg_kernel<HIDC, true><<<((size_t)N * 32 + 255) / 256, 256, 0, 0>>>(b1, nullptr, N);
    gemm_mma_kernel<OUTC, false><<<gemm_grid, 256, SMEM2, 0>>>(nullptr, W2, N, n_tiles);
    agg_kernel<OUTC, false><<<((size_t)N * 32 + 255) / 256, 256, 0, 0>>>(b2, out, N);
}

// round 15
// speedup vs baseline: 1.1986x; 1.1986x over previous
#include <cuda_runtime.h>
#include <cuda_fp16.h>
#include <cstdint>

// Problem shape (fixed by the dataset)
#define NMAX 100000
#define EMAX 1600000
#define INC 128
#define HIDC 128
#define OUTC 64

// ---------------- scratch (no allocation allowed) ----------------
__device__ __half g_h1[(size_t)NMAX * HIDC];  // x@W1 (unscaled, fp16)
__device__ __half g_hr[(size_t)NMAX * HIDC];  // relu(agg1 + b1), fp16
__device__ __half g_h2[(size_t)NMAX * OUTC];  // hr@W2 (unscaled, fp16)
__device__ float  g_dinv[NMAX];
__device__ float  g_edinv[EMAX];              // per-edge dinv[src], CSR order
__device__ int    g_cnt[2 * NMAX + 1];        // [0,N): in-deg, [NMAX,NMAX+N): out-deg, [2N]: total
__device__ int    g_rowstart[NMAX];
__device__ int    g_cursor[NMAX];
__device__ int    g_csr[EMAX];

// ---------------- helpers ----------------
__device__ __forceinline__ uint32_t pack_half2(float a, float b) {
    __half2 h = __floats2half2_rn(a, b);
    return *reinterpret_cast<uint32_t*>(&h);
}

__device__ __forceinline__ void mma_fp16(float* c, uint32_t a0, uint32_t a1,
                                         uint32_t a2, uint32_t a3,
                                         uint32_t b0, uint32_t b1) {
    asm volatile(
        "mma.sync.aligned.m16n8k16.row.col.f32.f16.f16.f32 "
        "{%0,%1,%2,%3}, {%4,%5,%6,%7}, {%8,%9}, {%0,%1,%2,%3};"
        : "+f"(c[0]), "+f"(c[1]), "+f"(c[2]), "+f"(c[3])
        : "r"(a0), "r"(a1), "r"(a2), "r"(a3), "r"(b0), "r"(b1));
}

// ---------------- CSR build (x4-unrolled atomics: independent chains) ----------------
__global__ void hist_kernel(const int* __restrict__ ei, int E) {
    int q = blockIdx.x * blockDim.x + threadIdx.x;
    int e0 = q * 4;
    if (e0 + 4 <= E) {
        int4 s = *(const int4*)(ei + e0);
        int4 d = *(const int4*)(ei + E + e0);
        atomicAdd(&g_cnt[NMAX + s.x], 1);
        atomicAdd(&g_cnt[NMAX + s.y], 1);
        atomicAdd(&g_cnt[NMAX + s.z], 1);
        atomicAdd(&g_cnt[NMAX + s.w], 1);
        atomicAdd(&g_cnt[d.x], 1);
        atomicAdd(&g_cnt[d.y], 1);
        atomicAdd(&g_cnt[d.z], 1);
        atomicAdd(&g_cnt[d.w], 1);
    } else {
        for (int e = e0; e < E; e++) {
            atomicAdd(&g_cnt[NMAX + ei[e]], 1);
            atomicAdd(&g_cnt[ei[E + e]], 1);
        }
    }
}

// Fused scan: block-local shuffle scan + one atomic segment allocation per block.
__global__ void alloc_scan_kernel(int n) {
    __shared__ int wsum[32];
    __shared__ int sbase;
    int t = threadIdx.x, lane = t & 31, w = t >> 5;
    int gid = blockIdx.x * 1024 + t;
    int v = (gid < n) ? g_cnt[gid] : 0;
    int x = v;
    #pragma unroll
    for (int d = 1; d < 32; d <<= 1) {
        int y = __shfl_up_sync(0xFFFFFFFFu, x, d);
        if (lane >= d) x += y;
    }
    if (lane == 31) wsum[w] = x;
    __syncthreads();
    if (w == 0) {
        int s = wsum[lane];
        int xs = s;
        #pragma unroll
        for (int d = 1; d < 32; d <<= 1) {
            int y = __shfl_up_sync(0xFFFFFFFFu, xs, d);
            if (lane >= d) xs += y;
        }
        wsum[lane] = xs - s;
    }
    __syncthreads();
    int excl = x - v + wsum[w];
    if (t == 1023) sbase = atomicAdd(&g_cnt[2 * NMAX], excl + v);
    __syncthreads();
    if (gid < n) {
        int base = sbase + excl;
        g_rowstart[gid] = base;
        g_cursor[gid] = base;
        int d = g_cnt[NMAX + gid];
        g_dinv[gid] = 1.0f / (float)(d > 1 ? d : 1);
    }
}

// scatter also materializes per-edge dinv (runs on the hidden CSR chain)
__global__ void scatter_kernel(const int* __restrict__ ei, int E) {
    int q = blockIdx.x * blockDim.x + threadIdx.x;
    int e0 = q * 4;
    if (e0 + 4 <= E) {
        int4 s = *(const int4*)(ei + e0);
        int4 d = *(const int4*)(ei + E + e0);
        float v0 = __ldg(&g_dinv[s.x]);
        float v1 = __ldg(&g_dinv[s.y]);
        float v2 = __ldg(&g_dinv[s.z]);
        float v3 = __ldg(&g_dinv[s.w]);
        int p0 = atomicAdd(&g_cursor[d.x], 1);
        int p1 = atomicAdd(&g_cursor[d.y], 1);
        int p2 = atomicAdd(&g_cursor[d.z], 1);
        int p3 = atomicAdd(&g_cursor[d.w], 1);
        g_csr[p0] = s.x;
        g_csr[p1] = s.y;
        g_csr[p2] = s.z;
        g_csr[p3] = s.w;
        g_edinv[p0] = v0;
        g_edinv[p1] = v1;
        g_edinv[p2] = v2;
        g_edinv[p3] = v3;
    } else {
        for (int e = e0; e < E; e++) {
            int ss = ei[e];
            int dd = ei[E + e];
            int pos = atomicAdd(&g_cursor[dd], 1);
            g_csr[pos] = ss;
            g_edinv[pos] = __ldg(&g_dinv[ss]);
        }
    }
}

// ---------------- fp16 mma.sync m16n8k16 GEMM (round-12 persistent, SAW=72) ----------
// out_fp16[M,N_] = A[M,128] @ W[128,N_]
// A smem: row stride SAW=72 words (conflict-free fragment LDS.64).
// B smem: unit (n,u) at word ((u>>3)*N_ + n)*8 + p(u&7), p(v)=v<4?2v:2(v-4)+1.
#define SAW 72

template <int N_, bool FIRST>
__global__ __launch_bounds__(256, 2)
void gemm_mma_kernel(const float* __restrict__ Ain, const float* __restrict__ W,
                     int M, int n_tiles) {
    extern __shared__ uint32_t smem[];
    uint32_t* As = smem;                  // 64 * SAW words
    uint32_t* Bs = smem + 64 * SAW;       // 64 * N_ words

    __half* __restrict__ out = FIRST ? g_h1 : g_h2;

    constexpr int HALF = N_ / 2;
    constexpr int NT = HALF / 8;          // 8 for N=128, 4 for N=64
    const int tid = threadIdx.x;
    const int wid = tid >> 5;             // 0..7
    const int lane = tid & 31;
    const int qr = lane >> 2;
    const int qc = lane & 3;
    const int rg = wid & 3;               // row group (16 rows)
    const int cg = wid >> 2;              // col half

    // ---- stage B once ----
    for (int uidx = tid; uidx < 64 * N_; uidx += 256) {
        int u = uidx / N_;
        int n = uidx - u * N_;
        uint32_t val = pack_half2(W[(size_t)(2 * u) * N_ + n], W[(size_t)(2 * u + 1) * N_ + n]);
        int v = u & 7;
        int p = (v < 4) ? (2 * v) : (2 * (v - 4) + 1);
        Bs[(((u >> 3) * N_ + n) << 3) + p] = val;
    }

    const int sg = lane >> 2;
    const int sj = lane & 3;

    auto load_row = [&](int gr, uint32_t& r0, uint32_t& r1) {
        if (gr >= M) { r0 = 0u; r1 = 0u; return; }
        if constexpr (FIRST) {
            float4 v = *(const float4*)(Ain + (size_t)gr * 128 + lane * 4);
            r0 = pack_half2(v.x, v.y);
            r1 = pack_half2(v.z, v.w);
        } else {
            uint2 u = *(const uint2*)(g_hr + (size_t)gr * 128 + lane * 4);
            r0 = u.x; r1 = u.y;
        }
    };

    uint32_t pr0[8], pr1[8];
    int t = blockIdx.x;
    if (t < n_tiles) {
        #pragma unroll
        for (int it = 0; it < 8; it++)
            load_row(t * 64 + wid + it * 8, pr0[it], pr1[it]);
    }
    __syncthreads();   // B staged

    for (; t < n_tiles; ) {
        // ---- STS: lane-pair (xor 2) exchange -> conflict-free STS.128 ----
        #pragma unroll
        for (int it = 0; it < 8; it++) {
            int r = wid + it * 8;
            uint32_t o0 = __shfl_xor_sync(0xFFFFFFFFu, pr0[it], 2);
            uint32_t o1 = __shfl_xor_sync(0xFFFFFFFFu, pr1[it], 2);
            if ((sj & 2) == 0) {
                uint4 st;
                st.x = pr0[it]; st.y = o0; st.z = pr1[it]; st.w = o1;
                *(uint4*)(As + r * SAW + sg * 8 + (sj & 1) * 4) = st;
            }
        }
        __syncthreads();

        // ---- prefetch next tile (overlaps compute) ----
        int tn = t + gridDim.x;
        if (tn < n_tiles) {
            #pragma unroll
            for (int it = 0; it < 8; it++)
                load_row(tn * 64 + wid + it * 8, pr0[it], pr1[it]);
        }

        // ---- compute: 8 k16-steps ----
        float acc[NT][4];
        #pragma unroll
        for (int nt = 0; nt < NT; nt++)
            #pragma unroll
            for (int j = 0; j < 4; j++) acc[nt][j] = 0.f;

        #pragma unroll
        for (int s = 0; s < 8; s++) {
            const uint32_t* pa = As + (rg * 16 + qr) * SAW + s * 8 + qc * 2;
            uint2 A0 = *(const uint2*)pa;              // {a0, a2}
            uint2 A1 = *(const uint2*)(pa + 8 * SAW);  // {a1, a3}
            const uint32_t* pb = Bs + (((s * N_) + cg * HALF + qr) << 3) + qc * 2;
            #pragma unroll
            for (int nt = 0; nt < NT; nt++) {
                uint2 B0 = *(const uint2*)(pb + (nt << 6));
                mma_fp16(acc[nt], A0.x, A1.x, A0.y, A1.y, B0.x, B0.y);
            }
        }

        // ---- epilogue: fp16 store ----
        {
            int r0 = t * 64 + rg * 16 + qr;
            int r1 = r0 + 8;
            #pragma unroll
            for (int nt = 0; nt < NT; nt++) {
                int c = cg * HALF + nt * 8 + qc * 2;
                if (r0 < M)
                    *(__half2*)(out + (size_t)r0 * N_ + c) = __floats2half2_rn(acc[nt][0], acc[nt][1]);
                if (r1 < M)
                    *(__half2*)(out + (size_t)r1 * N_ + c) = __floats2half2_rn(acc[nt][2], acc[nt][3]);
            }
        }
        __syncthreads();
        t = tn;
    }
}

// ---------------- aggregation: warp per dst node, 8-deep gather, edge-dinv ----------------
template <int C, bool FIRST>
__global__ void agg_kernel(const float* __restrict__ bias, float* __restrict__ outp, int n) {
    int gw = (blockIdx.x * blockDim.x + threadIdx.x) >> 5;
    int lane = threadIdx.x & 31;
    if (gw >= n) return;

    const __half* __restrict__ h = FIRST ? g_h1 : g_h2;

    int beg = g_rowstart[gw];
    int m = g_cnt[gw];   // in-degree

    if constexpr (C == 128) {
        size_t off = (size_t)lane * 4;
        float4 acc = make_float4(0.f, 0.f, 0.f, 0.f);
        int e = 0;
        for (; e + 8 <= m; e += 8) {
            int idx[8];
            uint2 u[8];
            float d[8];
            #pragma unroll
            for (int j = 0; j < 8; j++) idx[j] = g_csr[beg + e + j];
            #pragma unroll
            for (int j = 0; j < 8; j++) u[j] = *(const uint2*)(h + (size_t)idx[j] * C + off);
            #pragma unroll
            for (int j = 0; j < 8; j++) d[j] = g_edinv[beg + e + j];
            #pragma unroll
            for (int j = 0; j < 8; j++) {
                float2 a0 = __half22float2(*reinterpret_cast<__half2*>(&u[j].x));
                float2 a1 = __half22float2(*reinterpret_cast<__half2*>(&u[j].y));
                acc.x = fmaf(a0.x, d[j], acc.x);
                acc.y = fmaf(a0.y, d[j], acc.y);
                acc.z = fmaf(a1.x, d[j], acc.z);
                acc.w = fmaf(a1.y, d[j], acc.w);
            }
        }
        for (; e + 2 <= m; e += 2) {
            int s0 = g_csr[beg + e];
            int s1 = g_csr[beg + e + 1];
            uint2 u0 = *(const uint2*)(h + (size_t)s0 * C + off);
            uint2 u1 = *(const uint2*)(h + (size_t)s1 * C + off);
            float d0 = g_edinv[beg + e];
            float d1 = g_edinv[beg + e + 1];
            float2 a0 = __half22float2(*reinterpret_cast<__half2*>(&u0.x));
            float2 a1 = __half22float2(*reinterpret_cast<__half2*>(&u0.y));
            float2 b0 = __half22float2(*reinterpret_cast<__half2*>(&u1.x));
            float2 b1 = __half22float2(*reinterpret_cast<__half2*>(&u1.y));
            acc.x = fmaf(a0.x, d0, fmaf(b0.x, d1, acc.x));
            acc.y = fmaf(a0.y, d0, fmaf(b0.y, d1, acc.y));
            acc.z = fmaf(a1.x, d0, fmaf(b1.x, d1, acc.z));
            acc.w = fmaf(a1.y, d0, fmaf(b1.y, d1, acc.w));
        }
        if (e < m) {
            int s = g_csr[beg + e];
            float d = g_edinv[beg + e];
            uint2 u = *(const uint2*)(h + (size_t)s * C + off);
            float2 a0 = __half22float2(*reinterpret_cast<__half2*>(&u.x));
            float2 a1 = __half22float2(*reinterpret_cast<__half2*>(&u.y));
            acc.x = fmaf(a0.x, d, acc.x); acc.y = fmaf(a0.y, d, acc.y);
            acc.z = fmaf(a1.x, d, acc.z); acc.w = fmaf(a1.y, d, acc.w);
        }
        float4 bb = *(const float4*)(bias + lane * 4);
        acc.x += bb.x; acc.y += bb.y; acc.z += bb.z; acc.w += bb.w;
        if constexpr (FIRST) {
            acc.x = fmaxf(acc.x, 0.f); acc.y = fmaxf(acc.y, 0.f);
            acc.z = fmaxf(acc.z, 0.f); acc.w = fmaxf(acc.w, 0.f);
            uint2 st;
            *reinterpret_cast<__half2*>(&st.x) = __floats2half2_rn(acc.x, acc.y);
            *reinterpret_cast<__half2*>(&st.y) = __floats2half2_rn(acc.z, acc.w);
            *(uint2*)(g_hr + (size_t)gw * C + off) = st;
        } else {
            *(float4*)(outp + (size_t)gw * C + off) = acc;
        }
    } else {
        size_t off = (size_t)lane * 2;
        float2 acc = make_float2(0.f, 0.f);
        int e = 0;
        for (; e + 8 <= m; e += 8) {
            int idx[8];
            uint32_t u[8];
            float d[8];
            #pragma unroll
            for (int j = 0; j < 8; j++) idx[j] = g_csr[beg + e + j];
            #pragma unroll
            for (int j = 0; j < 8; j++) u[j] = *(const uint32_t*)(h + (size_t)idx[j] * C + off);
            #pragma unroll
            for (int j = 0; j < 8; j++) d[j] = g_edinv[beg + e + j];
            #pragma unroll
            for (int j = 0; j < 8; j++) {
                float2 a = __half22float2(*reinterpret_cast<__half2*>(&u[j]));
                acc.x = fmaf(a.x, d[j], acc.x);
                acc.y = fmaf(a.y, d[j], acc.y);
            }
        }
        for (; e < m; e++) {
            int s = g_csr[beg + e];
            float d = g_edinv[beg + e];
            uint32_t u = *(const uint32_t*)(h + (size_t)s * C + off);
            float2 a = __half22float2(*reinterpret_cast<__half2*>(&u));
            acc.x = fmaf(a.x, d, acc.x); acc.y = fmaf(a.y, d, acc.y);
        }
        float2 bb = *(const float2*)(bias + lane * 2);
        acc.x += bb.x; acc.y += bb.y;
        *(float2*)(outp + (size_t)gw * C + off) = acc;
    }
}

// ---------------- launch ----------------
extern "C" void kernel_launch(void* const* d_in, const int* in_sizes, int n_in,
                              void* d_out, int out_size) {
    const float* x  = (const float*)d_in[0];
    const int*   ei = (const int*)d_in[1];
    const float* W1 = (const float*)d_in[2];
    const float* b1 = (const float*)d_in[3];
    const float* W2 = (const float*)d_in[4];
    const float* b2 = (const float*)d_in[5];
    float* out = (float*)d_out;

    int N = in_sizes[0] / INC;   // 100000
    int E = in_sizes[1] / 2;     // 1600000

    int nb1k = (N + 1023) / 1024;
    int n_tiles = (N + 63) / 64;

    const int SMEM1 = (64 * SAW + 64 * HIDC) * 4;   // 51200 (~50KB)
    const int SMEM2 = (64 * SAW + 64 * OUTC) * 4;   // 34816 (~34KB)

    static int sm_count = 0;
    static cudaStream_t s2 = nullptr;
    static cudaEvent_t evFork = nullptr, evCsr = nullptr;
    static void *p_cnt = nullptr;
    static bool init_ok = false;
    if (!init_ok) {
        int dev = 0, c = 0;
        cudaGetDevice(&dev);
        if (cudaDeviceGetAttribute(&c, cudaDevAttrMultiProcessorCount, dev) != cudaSuccess || c <= 0)
            c = 148;
        sm_count = c;
        cudaFuncSetAttribute(gemm_mma_kernel<HIDC, true>,
                             cudaFuncAttributeMaxDynamicSharedMemorySize, SMEM1);
        cudaFuncSetAttribute(gemm_mma_kernel<OUTC, false>,
                             cudaFuncAttributeMaxDynamicSharedMemorySize, SMEM2);
        cudaStreamCreateWithFlags(&s2, cudaStreamNonBlocking);
        cudaEventCreateWithFlags(&evFork, cudaEventDisableTiming);
        cudaEventCreateWithFlags(&evCsr,  cudaEventDisableTiming);
        cudaGetSymbolAddress(&p_cnt, g_cnt);
        init_ok = true;
    }

    int gemm_grid = 2 * sm_count;   // 2 CTAs/SM

    // ---- fork: CSR chain on s2 (atomics/latency-bound), GEMM1 on main (DRAM/tensor) ----
    cudaEventRecord(evFork, 0);
    cudaStreamWaitEvent(s2, evFork, 0);

    cudaMemsetAsync(p_cnt, 0, (size_t)(2 * NMAX + 1) * sizeof(int), s2);
    hist_kernel<<<(E / 4 + 255) / 256 + 1, 256, 0, s2>>>(ei, E);
    alloc_scan_kernel<<<nb1k, 1024, 0, s2>>>(N);
    scatter_kernel<<<(E / 4 + 255) / 256 + 1, 256, 0, s2>>>(ei, E);
    cudaEventRecord(evCsr, s2);

    gemm_mma_kernel<HIDC, true><<<gemm_grid, 256, SMEM1, 0>>>(x, W1, N, n_tiles);

    // ---- join, then serial memory-bound tail ----
    cudaStreamWaitEvent(0, evCsr, 0);
    agg_kernel<HIDC, true><<<((size_t)N * 32 + 255) / 256, 256, 0, 0>>>(b1, nullptr, N);
    gemm_mma_kernel<OUTC, false><<<gemm_grid, 256, SMEM2, 0>>>(nullptr, W2, N, n_tiles);
    agg_kernel<OUTC, false><<<((size_t)N * 32 + 255) / 256, 256, 0, 0>>>(b2, out, N);
}

// round 16
// speedup vs baseline: 1.2426x; 1.0367x over previous
#include <cuda_runtime.h>
#include <cuda_fp16.h>
#include <cstdint>

// Problem shape (fixed by the dataset)
#define NMAX 100000
#define EMAX 1600000
#define INC 128
#define HIDC 128
#define OUTC 64

// ---------------- scratch (no allocation allowed) ----------------
__device__ __half g_h1[(size_t)NMAX * HIDC];  // x@W1 (unscaled, fp16)
__device__ __half g_hr[(size_t)NMAX * HIDC];  // relu(agg1 + b1), fp16
__device__ __half g_h2[(size_t)NMAX * OUTC];  // hr@W2 (unscaled, fp16)
__device__ float  g_dinv[NMAX];
__device__ int    g_cnt_in[NMAX];
__device__ int    g_cnt_out[NMAX];
__device__ int    g_rowstart[NMAX];
__device__ int    g_cursor[NMAX];
__device__ int    g_total;
__device__ int    g_csr[EMAX];

// ---------------- helpers ----------------
__device__ __forceinline__ uint32_t pack_half2(float a, float b) {
    __half2 h = __floats2half2_rn(a, b);
    return *reinterpret_cast<uint32_t*>(&h);
}

__device__ __forceinline__ void mma_fp16(float* c, uint32_t a0, uint32_t a1,
                                         uint32_t a2, uint32_t a3,
                                         uint32_t b0, uint32_t b1) {
    asm volatile(
        "mma.sync.aligned.m16n8k16.row.col.f32.f16.f16.f32 "
        "{%0,%1,%2,%3}, {%4,%5,%6,%7}, {%8,%9}, {%0,%1,%2,%3};"
        : "+f"(c[0]), "+f"(c[1]), "+f"(c[2]), "+f"(c[3])
        : "r"(a0), "r"(a1), "r"(a2), "r"(a3), "r"(b0), "r"(b1));
}

// ---------------- CSR build (x4-unrolled atomics: independent chains) ----------------
__global__ void hist_kernel(const int* __restrict__ ei, int E) {
    int q = blockIdx.x * blockDim.x + threadIdx.x;
    int e0 = q * 4;
    if (e0 + 4 <= E) {
        int4 s = *(const int4*)(ei + e0);
        int4 d = *(const int4*)(ei + E + e0);
        atomicAdd(&g_cnt_out[s.x], 1);
        atomicAdd(&g_cnt_out[s.y], 1);
        atomicAdd(&g_cnt_out[s.z], 1);
        atomicAdd(&g_cnt_out[s.w], 1);
        atomicAdd(&g_cnt_in[d.x], 1);
        atomicAdd(&g_cnt_in[d.y], 1);
        atomicAdd(&g_cnt_in[d.z], 1);
        atomicAdd(&g_cnt_in[d.w], 1);
    } else {
        for (int e = e0; e < E; e++) {
            atomicAdd(&g_cnt_out[ei[e]], 1);
            atomicAdd(&g_cnt_in[ei[E + e]], 1);
        }
    }
}

// Fused scan: block-local shuffle scan + one atomic segment allocation per block.
__global__ void alloc_scan_kernel(int n) {
    __shared__ int wsum[32];
    __shared__ int sbase;
    int t = threadIdx.x, lane = t & 31, w = t >> 5;
    int gid = blockIdx.x * 1024 + t;
    int v = (gid < n) ? g_cnt_in[gid] : 0;
    int x = v;
    #pragma unroll
    for (int d = 1; d < 32; d <<= 1) {
        int y = __shfl_up_sync(0xFFFFFFFFu, x, d);
        if (lane >= d) x += y;
    }
    if (lane == 31) wsum[w] = x;
    __syncthreads();
    if (w == 0) {
        int s = wsum[lane];
        int xs = s;
        #pragma unroll
        for (int d = 1; d < 32; d <<= 1) {
            int y = __shfl_up_sync(0xFFFFFFFFu, xs, d);
            if (lane >= d) xs += y;
        }
        wsum[lane] = xs - s;
    }
    __syncthreads();
    int excl = x - v + wsum[w];
    if (t == 1023) sbase = atomicAdd(&g_total, excl + v);
    __syncthreads();
    if (gid < n) {
        int base = sbase + excl;
        g_rowstart[gid] = base;
        g_cursor[gid] = base;
        int d = g_cnt_out[gid];
        g_dinv[gid] = 1.0f / (float)(d > 1 ? d : 1);
    }
}

__global__ void scatter_kernel(const int* __restrict__ ei, int E) {
    int q = blockIdx.x * blockDim.x + threadIdx.x;
    int e0 = q * 4;
    if (e0 + 4 <= E) {
        int4 s = *(const int4*)(ei + e0);
        int4 d = *(const int4*)(ei + E + e0);
        int p0 = atomicAdd(&g_cursor[d.x], 1);
        int p1 = atomicAdd(&g_cursor[d.y], 1);
        int p2 = atomicAdd(&g_cursor[d.z], 1);
        int p3 = atomicAdd(&g_cursor[d.w], 1);
        g_csr[p0] = s.x;
        g_csr[p1] = s.y;
        g_csr[p2] = s.z;
        g_csr[p3] = s.w;
    } else {
        for (int e = e0; e < E; e++) {
            int dd = ei[E + e];
            int pos = atomicAdd(&g_cursor[dd], 1);
            g_csr[pos] = ei[e];
        }
    }
}

// ---------------- fp16 mma.sync m16n8k16 GEMM (persistent, SAW=72) ----------
// out_fp16[M,N_] = A[M,128] @ W[128,N_]
// A smem: row stride SAW=72 words (conflict-free fragment LDS.64).
// B smem: unit (n,u) at word ((u>>3)*N_ + n)*8 + p(u&7), p(v)=v<4?2v:2(v-4)+1.
#define SAW 72

template <int N_, bool FIRST>
__global__ __launch_bounds__(256, 2)
void gemm_mma_kernel(const float* __restrict__ Ain, const float* __restrict__ W,
                     int M, int n_tiles) {
    extern __shared__ uint32_t smem[];
    uint32_t* As = smem;                  // 64 * SAW words
    uint32_t* Bs = smem + 64 * SAW;       // 64 * N_ words

    __half* __restrict__ out = FIRST ? g_h1 : g_h2;

    constexpr int HALF = N_ / 2;
    constexpr int NT = HALF / 8;          // 8 for N=128, 4 for N=64
    const int tid = threadIdx.x;
    const int wid = tid >> 5;             // 0..7
    const int lane = tid & 31;
    const int qr = lane >> 2;
    const int qc = lane & 3;
    const int rg = wid & 3;               // row group (16 rows)
    const int cg = wid >> 2;              // col half

    // ---- stage B once ----
    for (int uidx = tid; uidx < 64 * N_; uidx += 256) {
        int u = uidx / N_;
        int n = uidx - u * N_;
        uint32_t val = pack_half2(W[(size_t)(2 * u) * N_ + n], W[(size_t)(2 * u + 1) * N_ + n]);
        int v = u & 7;
        int p = (v < 4) ? (2 * v) : (2 * (v - 4) + 1);
        Bs[(((u >> 3) * N_ + n) << 3) + p] = val;
    }

    const int sg = lane >> 2;
    const int sj = lane & 3;

    auto load_row = [&](int gr, uint32_t& r0, uint32_t& r1) {
        if (gr >= M) { r0 = 0u; r1 = 0u; return; }
        if constexpr (FIRST) {
            float4 v = *(const float4*)(Ain + (size_t)gr * 128 + lane * 4);
            r0 = pack_half2(v.x, v.y);
            r1 = pack_half2(v.z, v.w);
        } else {
            uint2 u = *(const uint2*)(g_hr + (size_t)gr * 128 + lane * 4);
            r0 = u.x; r1 = u.y;
        }
    };

    uint32_t pr0[8], pr1[8];
    int t = blockIdx.x;
    if (t < n_tiles) {
        #pragma unroll
        for (int it = 0; it < 8; it++)
            load_row(t * 64 + wid + it * 8, pr0[it], pr1[it]);
    }
    __syncthreads();   // B staged

    for (; t < n_tiles; ) {
        // ---- STS: lane-pair (xor 2) exchange -> conflict-free STS.128 ----
        #pragma unroll
        for (int it = 0; it < 8; it++) {
            int r = wid + it * 8;
            uint32_t o0 = __shfl_xor_sync(0xFFFFFFFFu, pr0[it], 2);
            uint32_t o1 = __shfl_xor_sync(0xFFFFFFFFu, pr1[it], 2);
            if ((sj & 2) == 0) {
                uint4 st;
                st.x = pr0[it]; st.y = o0; st.z = pr1[it]; st.w = o1;
                *(uint4*)(As + r * SAW + sg * 8 + (sj & 1) * 4) = st;
            }
        }
        __syncthreads();

        // ---- prefetch next tile (overlaps compute) ----
        int tn = t + gridDim.x;
        if (tn < n_tiles) {
            #pragma unroll
            for (int it = 0; it < 8; it++)
                load_row(tn * 64 + wid + it * 8, pr0[it], pr1[it]);
        }

        // ---- compute: 8 k16-steps ----
        float acc[NT][4];
        #pragma unroll
        for (int nt = 0; nt < NT; nt++)
            #pragma unroll
            for (int j = 0; j < 4; j++) acc[nt][j] = 0.f;

        #pragma unroll
        for (int s = 0; s < 8; s++) {
            const uint32_t* pa = As + (rg * 16 + qr) * SAW + s * 8 + qc * 2;
            uint2 A0 = *(const uint2*)pa;              // {a0, a2}
            uint2 A1 = *(const uint2*)(pa + 8 * SAW);  // {a1, a3}
            const uint32_t* pb = Bs + (((s * N_) + cg * HALF + qr) << 3) + qc * 2;
            #pragma unroll
            for (int nt = 0; nt < NT; nt++) {
                uint2 B0 = *(const uint2*)(pb + (nt << 6));
                mma_fp16(acc[nt], A0.x, A1.x, A0.y, A1.y, B0.x, B0.y);
            }
        }

        // ---- epilogue: fp16 store ----
        {
            int r0 = t * 64 + rg * 16 + qr;
            int r1 = r0 + 8;
            #pragma unroll
            for (int nt = 0; nt < NT; nt++) {
                int c = cg * HALF + nt * 8 + qc * 2;
                if (r0 < M)
                    *(__half2*)(out + (size_t)r0 * N_ + c) = __floats2half2_rn(acc[nt][0], acc[nt][1]);
                if (r1 < M)
                    *(__half2*)(out + (size_t)r1 * N_ + c) = __floats2half2_rn(acc[nt][2], acc[nt][3]);
            }
        }
        __syncthreads();
        t = tn;
    }
}

// ---------------- aggregation: warp per dst node, 8-deep gather, dinv __ldg ----------------
template <int C, bool FIRST>
__global__ void agg_kernel(const float* __restrict__ bias, float* __restrict__ outp, int n) {
    int gw = (blockIdx.x * blockDim.x + threadIdx.x) >> 5;
    int lane = threadIdx.x & 31;
    if (gw >= n) return;

    const __half* __restrict__ h = FIRST ? g_h1 : g_h2;

    int beg = g_rowstart[gw];
    int m = g_cnt_in[gw];

    if constexpr (C == 128) {
        size_t off = (size_t)lane * 4;
        float4 acc = make_float4(0.f, 0.f, 0.f, 0.f);
        int e = 0;
        for (; e + 8 <= m; e += 8) {
            int idx[8];
            uint2 u[8];
            float d[8];
            #pragma unroll
            for (int j = 0; j < 8; j++) idx[j] = g_csr[beg + e + j];
            #pragma unroll
            for (int j = 0; j < 8; j++) u[j] = *(const uint2*)(h + (size_t)idx[j] * C + off);
            #pragma unroll
            for (int j = 0; j < 8; j++) d[j] = __ldg(&g_dinv[idx[j]]);
            #pragma unroll
            for (int j = 0; j < 8; j++) {
                float2 a0 = __half22float2(*reinterpret_cast<__half2*>(&u[j].x));
                float2 a1 = __half22float2(*reinterpret_cast<__half2*>(&u[j].y));
                acc.x = fmaf(a0.x, d[j], acc.x);
                acc.y = fmaf(a0.y, d[j], acc.y);
                acc.z = fmaf(a1.x, d[j], acc.z);
                acc.w = fmaf(a1.y, d[j], acc.w);
            }
        }
        for (; e + 2 <= m; e += 2) {
            int s0 = g_csr[beg + e];
            int s1 = g_csr[beg + e + 1];
            uint2 u0 = *(const uint2*)(h + (size_t)s0 * C + off);
            uint2 u1 = *(const uint2*)(h + (size_t)s1 * C + off);
            float d0 = __ldg(&g_dinv[s0]);
            float d1 = __ldg(&g_dinv[s1]);
            float2 a0 = __half22float2(*reinterpret_cast<__half2*>(&u0.x));
            float2 a1 = __half22float2(*reinterpret_cast<__half2*>(&u0.y));
            float2 b0 = __half22float2(*reinterpret_cast<__half2*>(&u1.x));
            float2 b1 = __half22float2(*reinterpret_cast<__half2*>(&u1.y));
            acc.x = fmaf(a0.x, d0, fmaf(b0.x, d1, acc.x));
            acc.y = fmaf(a0.y, d0, fmaf(b0.y, d1, acc.y));
            acc.z = fmaf(a1.x, d0, fmaf(b1.x, d1, acc.z));
            acc.w = fmaf(a1.y, d0, fmaf(b1.y, d1, acc.w));
        }
        if (e < m) {
            int s = g_csr[beg + e];
            float d = __ldg(&g_dinv[s]);
            uint2 u = *(const uint2*)(h + (size_t)s * C + off);
            float2 a0 = __half22float2(*reinterpret_cast<__half2*>(&u.x));
            float2 a1 = __half22float2(*reinterpret_cast<__half2*>(&u.y));
            acc.x = fmaf(a0.x, d, acc.x); acc.y = fmaf(a0.y, d, acc.y);
            acc.z = fmaf(a1.x, d, acc.z); acc.w = fmaf(a1.y, d, acc.w);
        }
        float4 bb = *(const float4*)(bias + lane * 4);
        acc.x += bb.x; acc.y += bb.y; acc.z += bb.z; acc.w += bb.w;
        if constexpr (FIRST) {
            acc.x = fmaxf(acc.x, 0.f); acc.y = fmaxf(acc.y, 0.f);
            acc.z = fmaxf(acc.z, 0.f); acc.w = fmaxf(acc.w, 0.f);
            uint2 st;
            *reinterpret_cast<__half2*>(&st.x) = __floats2half2_rn(acc.x, acc.y);
            *reinterpret_cast<__half2*>(&st.y) = __floats2half2_rn(acc.z, acc.w);
            *(uint2*)(g_hr + (size_t)gw * C + off) = st;
        } else {
            *(float4*)(outp + (size_t)gw * C + off) = acc;
        }
    } else {
        size_t off = (size_t)lane * 2;
        float2 acc = make_float2(0.f, 0.f);
        int e = 0;
        for (; e + 8 <= m; e += 8) {
            int idx[8];
            uint32_t u[8];
            float d[8];
            #pragma unroll
            for (int j = 0; j < 8; j++) idx[j] = g_csr[beg + e + j];
            #pragma unroll
            for (int j = 0; j < 8; j++) u[j] = *(const uint32_t*)(h + (size_t)idx[j] * C + off);
            #pragma unroll
            for (int j = 0; j < 8; j++) d[j] = __ldg(&g_dinv[idx[j]]);
            #pragma unroll
            for (int j = 0; j < 8; j++) {
                float2 a = __half22float2(*reinterpret_cast<__half2*>(&u[j]));
                acc.x = fmaf(a.x, d[j], acc.x);
                acc.y = fmaf(a.y, d[j], acc.y);
            }
        }
        for (; e < m; e++) {
            int s = g_csr[beg + e];
            float d = __ldg(&g_dinv[s]);
            uint32_t u = *(const uint32_t*)(h + (size_t)s * C + off);
            float2 a = __half22float2(*reinterpret_cast<__half2*>(&u));
            acc.x = fmaf(a.x, d, acc.x); acc.y = fmaf(a.y, d, acc.y);
        }
        float2 bb = *(const float2*)(bias + lane * 2);
        acc.x += bb.x; acc.y += bb.y;
        *(float2*)(outp + (size_t)gw * C + off) = acc;
    }
}

// ---------------- launch ----------------
extern "C" void kernel_launch(void* const* d_in, const int* in_sizes, int n_in,
                              void* d_out, int out_size) {
    const float* x  = (const float*)d_in[0];
    const int*   ei = (const int*)d_in[1];
    const float* W1 = (const float*)d_in[2];
    const float* b1 = (const float*)d_in[3];
    const float* W2 = (const float*)d_in[4];
    const float* b2 = (const float*)d_in[5];
    float* out = (float*)d_out;

    int N = in_sizes[0] / INC;   // 100000
    int E = in_sizes[1] / 2;     // 1600000

    int nb1k = (N + 1023) / 1024;
    int n_tiles = (N + 63) / 64;

    const int SMEM1 = (64 * SAW + 64 * HIDC) * 4;   // 51200 (~50KB)
    const int SMEM2 = (64 * SAW + 64 * OUTC) * 4;   // 34816 (~34KB)

    static int sm_count = 0;
    static cudaStream_t s2 = nullptr;
    static cudaEvent_t evFork = nullptr, evCsr = nullptr;
    static void *p_cnt_in = nullptr, *p_cnt_out = nullptr, *p_total = nullptr;
    static bool init_ok = false;
    if (!init_ok) {
        int dev = 0, c = 0;
        cudaGetDevice(&dev);
        if (cudaDeviceGetAttribute(&c, cudaDevAttrMultiProcessorCount, dev) != cudaSuccess || c <= 0)
            c = 148;
        sm_count = c;
        cudaFuncSetAttribute(gemm_mma_kernel<HIDC, true>,
                             cudaFuncAttributeMaxDynamicSharedMemorySize, SMEM1);
        cudaFuncSetAttribute(gemm_mma_kernel<OUTC, false>,
                             cudaFuncAttributeMaxDynamicSharedMemorySize, SMEM2);
        cudaStreamCreateWithFlags(&s2, cudaStreamNonBlocking);
        cudaEventCreateWithFlags(&evFork, cudaEventDisableTiming);
        cudaEventCreateWithFlags(&evCsr,  cudaEventDisableTiming);
        cudaGetSymbolAddress(&p_cnt_in,  g_cnt_in);
        cudaGetSymbolAddress(&p_cnt_out, g_cnt_out);
        cudaGetSymbolAddress(&p_total,   g_total);
        init_ok = true;
    }

    int gemm_grid = 2 * sm_count;   // 2 CTAs/SM

    // ---- fork: CSR chain on s2 (atomics/latency-bound), GEMM1 on main (DRAM/tensor) ----
    cudaEventRecord(evFork, 0);
    cudaStreamWaitEvent(s2, evFork, 0);

    cudaMemsetAsync(p_cnt_in,  0, (size_t)N * sizeof(int), s2);
    cudaMemsetAsync(p_cnt_out, 0, (size_t)N * sizeof(int), s2);
    cudaMemsetAsync(p_total,   0, sizeof(int), s2);
    hist_kernel<<<(E / 4 + 255) / 256 + 1, 256, 0, s2>>>(ei, E);
    alloc_scan_kernel<<<nb1k, 1024, 0, s2>>>(N);
    scatter_kernel<<<(E / 4 + 255) / 256 + 1, 256, 0, s2>>>(ei, E);
    cudaEventRecord(evCsr, s2);

    gemm_mma_kernel<HIDC, true><<<gemm_grid, 256, SMEM1, 0>>>(x, W1, N, n_tiles);

    // ---- join, then serial memory-bound tail ----
    cudaStreamWaitEvent(0, evCsr, 0);
    agg_kernel<HIDC, true><<<((size_t)N * 32 + 255) / 256, 256, 0, 0>>>(b1, nullptr, N);
    gemm_mma_kernel<OUTC, false><<<gemm_grid, 256, SMEM2, 0>>>(nullptr, W2, N, n_tiles);
    agg_kernel<OUTC, false><<<((size_t)N * 32 + 255) / 256, 256, 0, 0>>>(b2, out, N);
}